// round 1
// baseline (speedup 1.0000x reference)
#include <cuda_runtime.h>

// Problem constants
constexpr int Bn = 4;
constexpr int Sn = 2048;
constexpr int Dn = 1024;
constexpr int Hn = 16;
constexpr int HSn = 64;     // head size

// Scratch: Q,K,V in [B,H,S,HS], attention output in [B,S,D]
__device__ float g_q[Bn * Hn * Sn * HSn];
__device__ float g_k[Bn * Hn * Sn * HSn];
__device__ float g_v[Bn * Hn * Sn * HSn];
__device__ float g_attn[Bn * Sn * Dn];

// ---------------------------------------------------------------------------
// Kernel 1: per-head QKV projection.
// For each (b,h): out[S,HS] = X_b[S,D] @ W_h[D,HS]
// grid = (S/64, B*H, 3), block = 256 (16x16 threads, 4x4 microtile)
// ---------------------------------------------------------------------------
__global__ __launch_bounds__(256) void proj_kernel(
    const float* __restrict__ X,
    const float* __restrict__ Wq,
    const float* __restrict__ Wk,
    const float* __restrict__ Wv)
{
    const int qt = blockIdx.x;          // query-row tile (64 rows)
    const int bh = blockIdx.y;          // b*H + h
    const int which = blockIdx.z;       // 0=q 1=k 2=v
    const int b = bh >> 4;
    const int h = bh & 15;

    const float* W;
    float* outbuf;
    if (which == 0)      { W = Wq; outbuf = g_q; }
    else if (which == 1) { W = Wk; outbuf = g_k; }
    else                 { W = Wv; outbuf = g_v; }
    W += h * Dn * HSn;
    float* C = outbuf + (bh * Sn + qt * 64) * HSn;
    const float* A = X + b * Sn * Dn + (qt * 64) * Dn;

    __shared__ float As[16][68];   // [k][m], padded for float4 + conflicts
    __shared__ float Bs[16][64];   // [k][n]

    const int tid = threadIdx.x;
    const int ty = tid >> 4, tx = tid & 15;
    const int arow = tid >> 2;            // 0..63
    const int acol = (tid & 3) * 4;       // 0,4,8,12
    const int kr = tid >> 4;              // 0..15
    const int nc = (tid & 15) * 4;        // 0..60

    float acc[4][4] = {};

    for (int k0 = 0; k0 < Dn; k0 += 16) {
        float4 av = *(const float4*)(A + arow * Dn + k0 + acol);
        As[acol + 0][arow] = av.x;
        As[acol + 1][arow] = av.y;
        As[acol + 2][arow] = av.z;
        As[acol + 3][arow] = av.w;
        *(float4*)&Bs[kr][nc] = *(const float4*)(W + (k0 + kr) * HSn + nc);
        __syncthreads();

        #pragma unroll
        for (int k = 0; k < 16; k++) {
            float4 a = *(const float4*)&As[k][ty * 4];
            float4 bb = *(const float4*)&Bs[k][tx * 4];
            float ar[4] = {a.x, a.y, a.z, a.w};
            float br[4] = {bb.x, bb.y, bb.z, bb.w};
            #pragma unroll
            for (int i = 0; i < 4; i++)
                #pragma unroll
                for (int j = 0; j < 4; j++)
                    acc[i][j] += ar[i] * br[j];
        }
        __syncthreads();
    }

    #pragma unroll
    for (int i = 0; i < 4; i++) {
        *(float4*)&C[(ty * 4 + i) * HSn + tx * 4] =
            make_float4(acc[i][0], acc[i][1], acc[i][2], acc[i][3]);
    }
}

// ---------------------------------------------------------------------------
// Kernel 2: causal flash attention per (b,h).
// BM=64 queries per block, BN=32 keys per step, HS=64. Online softmax.
// grid = (S/64, B*H), block = 256
// ---------------------------------------------------------------------------
__global__ __launch_bounds__(256) void attn_kernel()
{
    const int qt = blockIdx.x;    // 0..31
    const int bh = blockIdx.y;    // 0..63
    const int b = bh >> 4;
    const int h = bh & 15;
    const int q0 = qt * 64;

    const float* Q = g_q + (bh * Sn + q0) * HSn;
    const float* K = g_k + bh * Sn * HSn;
    const float* V = g_v + bh * Sn * HSn;

    __shared__ float Qs[64][66];    // [e][m]  (scaled by 1/sqrt(HS))
    __shared__ float Ks[64][36];    // [e][n]
    __shared__ float Vs[32][68];    // [n][e]
    __shared__ float Ss[64][33];    // [m][n]  scores -> probabilities
    __shared__ float m_s[64], l_s[64], alpha_s[64];
    __shared__ float pmax[64][4], psum[64][4];

    const int tid = threadIdx.x;

    // Load Q tile transposed, pre-scaled by HS^-0.5 = 0.125
    {
        const int row = tid >> 2;            // 0..63
        const int e0 = (tid & 3) * 16;
        #pragma unroll
        for (int i = 0; i < 16; i += 4) {
            float4 v = *(const float4*)(Q + row * HSn + e0 + i);
            Qs[e0 + i + 0][row] = v.x * 0.125f;
            Qs[e0 + i + 1][row] = v.y * 0.125f;
            Qs[e0 + i + 2][row] = v.z * 0.125f;
            Qs[e0 + i + 3][row] = v.w * 0.125f;
        }
    }
    if (tid < 64) { m_s[tid] = -1e30f; l_s[tid] = 0.0f; }

    // PV / output mapping: (ty,tx) owns rows ty*4..+3, dims tx*4..+3
    const int ty = tid >> 4, tx = tid & 15;
    float o[4][4] = {};

    // Score mapping: thread owns 2 rows x 4 key-cols
    const int sm0 = (tid >> 3) * 2;      // 0,2,..,62
    const int sn0 = (tid & 7) * 4;       // 0..28

    const int jmax = 2 * qt + 1;
    for (int j = 0; j <= jmax; j++) {
        const int k0 = j * 32;
        __syncthreads();   // Q ready (iter 0) / previous PV done with Vs,Ss,alpha

        // Load K (transposed) and V tiles
        {
            const int n = tid >> 3;            // 0..31
            const int e0 = (tid & 7) * 8;
            const float* kp = K + (k0 + n) * HSn + e0;
            float4 k0v = *(const float4*)(kp);
            float4 k1v = *(const float4*)(kp + 4);
            Ks[e0 + 0][n] = k0v.x; Ks[e0 + 1][n] = k0v.y;
            Ks[e0 + 2][n] = k0v.z; Ks[e0 + 3][n] = k0v.w;
            Ks[e0 + 4][n] = k1v.x; Ks[e0 + 5][n] = k1v.y;
            Ks[e0 + 6][n] = k1v.z; Ks[e0 + 7][n] = k1v.w;
            const float* vp = V + (k0 + n) * HSn + e0;
            *(float4*)&Vs[n][e0]     = *(const float4*)(vp);
            *(float4*)&Vs[n][e0 + 4] = *(const float4*)(vp + 4);
        }
        __syncthreads();

        // S = (Q * scale) @ K^T
        float sacc[2][4] = {};
        #pragma unroll
        for (int e = 0; e < 64; e++) {
            float2 qa = *(const float2*)&Qs[e][sm0];
            float4 kb = *(const float4*)&Ks[e][sn0];
            sacc[0][0] += qa.x * kb.x; sacc[0][1] += qa.x * kb.y;
            sacc[0][2] += qa.x * kb.z; sacc[0][3] += qa.x * kb.w;
            sacc[1][0] += qa.y * kb.x; sacc[1][1] += qa.y * kb.y;
            sacc[1][2] += qa.y * kb.z; sacc[1][3] += qa.y * kb.w;
        }
        // Causal mask + store scores
        #pragma unroll
        for (int i = 0; i < 2; i++) {
            const int qg = q0 + sm0 + i;
            #pragma unroll
            for (int jj = 0; jj < 4; jj++) {
                const int kg = k0 + sn0 + jj;
                Ss[sm0 + i][sn0 + jj] = (kg <= qg) ? sacc[i][jj] : -1e30f;
            }
        }
        __syncthreads();

        // Row max (partial, 4 threads per row)
        {
            const int r = tid >> 2, qd = tid & 3;
            float mx = -1e30f;
            #pragma unroll
            for (int c = 0; c < 8; c++) mx = fmaxf(mx, Ss[r][qd * 8 + c]);
            pmax[r][qd] = mx;
        }
        __syncthreads();
        if (tid < 64) {
            float mx = fmaxf(fmaxf(pmax[tid][0], pmax[tid][1]),
                             fmaxf(pmax[tid][2], pmax[tid][3]));
            float mnew = fmaxf(m_s[tid], mx);
            alpha_s[tid] = __expf(m_s[tid] - mnew);
            m_s[tid] = mnew;
        }
        __syncthreads();
        // exp + partial row sum (in place)
        {
            const int r = tid >> 2, qd = tid & 3;
            const float mr = m_s[r];
            float sum = 0.0f;
            #pragma unroll
            for (int c = 0; c < 8; c++) {
                float p = __expf(Ss[r][qd * 8 + c] - mr);
                Ss[r][qd * 8 + c] = p;
                sum += p;
            }
            psum[r][qd] = sum;
        }
        __syncthreads();
        if (tid < 64) {
            l_s[tid] = l_s[tid] * alpha_s[tid] +
                       psum[tid][0] + psum[tid][1] + psum[tid][2] + psum[tid][3];
        }

        // O = O*alpha + P @ V
        #pragma unroll
        for (int i = 0; i < 4; i++) {
            const float a = alpha_s[ty * 4 + i];
            o[i][0] *= a; o[i][1] *= a; o[i][2] *= a; o[i][3] *= a;
        }
        #pragma unroll
        for (int n = 0; n < 32; n++) {
            float4 vv = *(const float4*)&Vs[n][tx * 4];
            #pragma unroll
            for (int i = 0; i < 4; i++) {
                const float p = Ss[ty * 4 + i][n];
                o[i][0] += p * vv.x; o[i][1] += p * vv.y;
                o[i][2] += p * vv.z; o[i][3] += p * vv.w;
            }
        }
    }
    __syncthreads();   // l_s final values visible

    // Normalize and write to concat-head layout [B,S,D]
    float* Obuf = g_attn + (b * Sn + q0) * Dn + h * HSn;
    #pragma unroll
    for (int i = 0; i < 4; i++) {
        const float inv = 1.0f / l_s[ty * 4 + i];
        *(float4*)&Obuf[(ty * 4 + i) * Dn + tx * 4] =
            make_float4(o[i][0] * inv, o[i][1] * inv, o[i][2] * inv, o[i][3] * inv);
    }
}

// ---------------------------------------------------------------------------
// Kernel 3: output projection. out[8192,1024] = attn @ Wo + bo
// grid = (D/64, B*S/64), block = 256
// ---------------------------------------------------------------------------
__global__ __launch_bounds__(256) void outproj_kernel(
    const float* __restrict__ Wo,
    const float* __restrict__ bo,
    float* __restrict__ out)
{
    const int nt = blockIdx.x;   // 0..15
    const int mt = blockIdx.y;   // 0..127
    const float* A = g_attn + mt * 64 * Dn;
    const float* Bp = Wo + nt * 64;
    float* C = out + mt * 64 * Dn + nt * 64;

    __shared__ float As[16][68];
    __shared__ float Bs[16][64];

    const int tid = threadIdx.x;
    const int ty = tid >> 4, tx = tid & 15;
    const int arow = tid >> 2;
    const int acol = (tid & 3) * 4;
    const int kr = tid >> 4;
    const int nc = (tid & 15) * 4;

    float acc[4][4] = {};

    for (int k0 = 0; k0 < Dn; k0 += 16) {
        float4 av = *(const float4*)(A + arow * Dn + k0 + acol);
        As[acol + 0][arow] = av.x;
        As[acol + 1][arow] = av.y;
        As[acol + 2][arow] = av.z;
        As[acol + 3][arow] = av.w;
        *(float4*)&Bs[kr][nc] = *(const float4*)(Bp + (k0 + kr) * Dn + nc);
        __syncthreads();

        #pragma unroll
        for (int k = 0; k < 16; k++) {
            float4 a = *(const float4*)&As[k][ty * 4];
            float4 bb = *(const float4*)&Bs[k][tx * 4];
            float ar[4] = {a.x, a.y, a.z, a.w};
            float br[4] = {bb.x, bb.y, bb.z, bb.w};
            #pragma unroll
            for (int i = 0; i < 4; i++)
                #pragma unroll
                for (int j = 0; j < 4; j++)
                    acc[i][j] += ar[i] * br[j];
        }
        __syncthreads();
    }

    const float4 bias = *(const float4*)(bo + nt * 64 + tx * 4);
    #pragma unroll
    for (int i = 0; i < 4; i++) {
        *(float4*)&C[(ty * 4 + i) * Dn + tx * 4] =
            make_float4(acc[i][0] + bias.x, acc[i][1] + bias.y,
                        acc[i][2] + bias.z, acc[i][3] + bias.w);
    }
}

// ---------------------------------------------------------------------------
extern "C" void kernel_launch(void* const* d_in, const int* in_sizes, int n_in,
                              void* d_out, int out_size)
{
    const float* X  = (const float*)d_in[0];   // [B,S,D]
    const float* Wq = (const float*)d_in[1];   // [H,D,HS]
    const float* Wk = (const float*)d_in[2];
    const float* Wv = (const float*)d_in[3];
    const float* Wo = (const float*)d_in[4];   // [D,D]
    const float* bo = (const float*)d_in[5];   // [D]
    float* out = (float*)d_out;                // [B,S,D]

    proj_kernel<<<dim3(Sn / 64, Bn * Hn, 3), 256>>>(X, Wq, Wk, Wv);
    attn_kernel<<<dim3(Sn / 64, Bn * Hn), 256>>>();
    outproj_kernel<<<dim3(Dn / 64, (Bn * Sn) / 64), 256>>>(Wo, bo, out);
}

// round 3
// speedup vs baseline: 2.5683x; 2.5683x over previous
#include <cuda_runtime.h>
#include <cstdint>

// Problem constants
constexpr int Bn = 4;
constexpr int Sn = 2048;
constexpr int Dn = 1024;
constexpr int Hn = 16;
constexpr int HSn = 64;     // head size

// Scratch: Q,K,V in [B,H,S,HS], attention output in [B,S,D]
__device__ float g_q[Bn * Hn * Sn * HSn];
__device__ float g_k[Bn * Hn * Sn * HSn];
__device__ float g_v[Bn * Hn * Sn * HSn];
__device__ float g_attn[Bn * Sn * Dn];

// ---------------------------------------------------------------------------
// tf32 helpers
// ---------------------------------------------------------------------------
__device__ __forceinline__ uint32_t f2tf(float x) {
    uint32_t r;
    asm("cvt.rna.tf32.f32 %0, %1;" : "=r"(r) : "f"(x));
    return r;
}

// D += A @ B, m16n8k8 tf32. c: 4 floats, a: 4 regs, b: 2 regs.
__device__ __forceinline__ void mma_tf32(float c[4],
                                         uint32_t a0, uint32_t a1, uint32_t a2, uint32_t a3,
                                         uint32_t b0, uint32_t b1) {
    asm volatile(
        "mma.sync.aligned.m16n8k8.row.col.f32.tf32.tf32.f32 "
        "{%0,%1,%2,%3}, {%4,%5,%6,%7}, {%8,%9}, {%0,%1,%2,%3};\n"
        : "+f"(c[0]), "+f"(c[1]), "+f"(c[2]), "+f"(c[3])
        : "r"(a0), "r"(a1), "r"(a2), "r"(a3), "r"(b0), "r"(b1));
}

// ---------------------------------------------------------------------------
// Kernel 1: per-head QKV projection via tf32 MMA.
// For each (b,h): out[S,HS] = X_b[S,D] @ W_h[D,HS]
// grid = (S/128, B*H, 3), block = 256 (8 warps, 4x2; warp tile 32x32)
// ---------------------------------------------------------------------------
__global__ __launch_bounds__(256) void proj_tc(
    const float* __restrict__ X,
    const float* __restrict__ Wq,
    const float* __restrict__ Wk,
    const float* __restrict__ Wv)
{
    const int mt0 = blockIdx.x * 128;
    const int bh = blockIdx.y;
    const int which = blockIdx.z;
    const int b = bh >> 4;
    const int h = bh & 15;

    const float* W;
    float* outb;
    if (which == 0)      { W = Wq; outb = g_q; }
    else if (which == 1) { W = Wk; outb = g_k; }
    else                 { W = Wv; outb = g_v; }
    W += h * Dn * HSn;
    const float* A = X + b * Sn * Dn + mt0 * Dn;
    float* C = outb + (bh * Sn + mt0) * HSn;

    __shared__ uint32_t As[128][36];   // [m][k]
    __shared__ uint32_t Bs[32][68];    // [k][n]

    const int tid = threadIdx.x;
    const int lane = tid & 31;
    const int w = tid >> 5;
    const int wm = w >> 1;     // 0..3
    const int wn = w & 1;      // 0..1
    const int g = lane >> 2;   // 0..7
    const int t4 = lane & 3;   // 0..3

    const int ar = tid >> 1;            // 0..127
    const int ac = (tid & 1) * 16;
    const int bk = tid >> 3;            // 0..31
    const int bn = (tid & 7) * 8;

    float c[2][4][4] = {};

    for (int kc = 0; kc < Dn; kc += 32) {
        {
            const float4* src = (const float4*)(A + ar * Dn + kc + ac);
            #pragma unroll
            for (int q = 0; q < 4; q++) {
                float4 v = src[q];
                *(uint4*)&As[ar][ac + q * 4] =
                    make_uint4(f2tf(v.x), f2tf(v.y), f2tf(v.z), f2tf(v.w));
            }
        }
        {
            const float* wp = W + (kc + bk) * HSn + bn;
            float4 v0 = *(const float4*)(wp);
            float4 v1 = *(const float4*)(wp + 4);
            *(uint4*)&Bs[bk][bn]     = make_uint4(f2tf(v0.x), f2tf(v0.y), f2tf(v0.z), f2tf(v0.w));
            *(uint4*)&Bs[bk][bn + 4] = make_uint4(f2tf(v1.x), f2tf(v1.y), f2tf(v1.z), f2tf(v1.w));
        }
        __syncthreads();

        #pragma unroll
        for (int ks = 0; ks < 4; ks++) {
            uint32_t a[2][4];
            #pragma unroll
            for (int mt = 0; mt < 2; mt++) {
                const int r = wm * 32 + mt * 16 + g;
                const int k = ks * 8 + t4;
                a[mt][0] = As[r][k];
                a[mt][1] = As[r + 8][k];
                a[mt][2] = As[r][k + 4];
                a[mt][3] = As[r + 8][k + 4];
            }
            #pragma unroll
            for (int nt = 0; nt < 4; nt++) {
                const int n = wn * 32 + nt * 8 + g;
                uint32_t b0 = Bs[ks * 8 + t4][n];
                uint32_t b1 = Bs[ks * 8 + t4 + 4][n];
                mma_tf32(c[0][nt], a[0][0], a[0][1], a[0][2], a[0][3], b0, b1);
                mma_tf32(c[1][nt], a[1][0], a[1][1], a[1][2], a[1][3], b0, b1);
            }
        }
        __syncthreads();
    }

    #pragma unroll
    for (int mt = 0; mt < 2; mt++) {
        const int r = wm * 32 + mt * 16 + g;
        #pragma unroll
        for (int nt = 0; nt < 4; nt++) {
            const int n = wn * 32 + nt * 8 + 2 * t4;
            *(float2*)&C[r * HSn + n]       = make_float2(c[mt][nt][0], c[mt][nt][1]);
            *(float2*)&C[(r + 8) * HSn + n] = make_float2(c[mt][nt][2], c[mt][nt][3]);
        }
    }
}

// ---------------------------------------------------------------------------
// Kernel 2: causal flash attention via tf32 MMA.
// BM=128 queries, BN=32 keys. 8 warps stacked along M (16 rows each).
// Each warp owns the FULL key tile for its rows -> softmax stats are
// warp-local (quad shuffles). Q fragments in registers. P via per-warp smem.
// grid = (S/128, B*H), block = 256
// ---------------------------------------------------------------------------
__global__ __launch_bounds__(256) void attn_tc()
{
    const int qt = blockIdx.x;    // 0..15
    const int bh = blockIdx.y;    // 0..63
    const int b = bh >> 4;
    const int h = bh & 15;
    const int q0 = qt * 128;

    const float* Q = g_q + (bh * Sn + q0) * HSn;
    const float* K = g_k + bh * Sn * HSn;
    const float* V = g_v + bh * Sn * HSn;

    __shared__ uint32_t Ks[32][68];   // [n][e]; B-frag bank = 4g+t4 (perfect)
    __shared__ uint32_t Vs[32][72];   // [k][hs]; B-frag bank = 8t4+g (perfect)
    __shared__ uint32_t Ps[128][36];  // [m][k] per-warp; A-frag bank = 4g+t4

    const int tid = threadIdx.x;
    const int lane = tid & 31;
    const int w = tid >> 5;
    const int g = lane >> 2;
    const int t4 = lane & 3;
    const int wrow = w * 16;          // warp's first row within the 128-row tile

    // Q fragments in registers (prescaled by HS^-0.5 = 0.125, tf32)
    uint32_t qf[8][4];
    {
        const float* Qw = Q + (wrow + g) * HSn;
        #pragma unroll
        for (int ks = 0; ks < 8; ks++) {
            const int e = ks * 8 + t4;
            qf[ks][0] = f2tf(Qw[e] * 0.125f);
            qf[ks][1] = f2tf(Qw[8 * HSn + e] * 0.125f);
            qf[ks][2] = f2tf(Qw[e + 4] * 0.125f);
            qf[ks][3] = f2tf(Qw[8 * HSn + e + 4] * 0.125f);
        }
    }

    float o[8][4] = {};
    float m0 = -1e30f, m1 = -1e30f, l0 = 0.0f, l1 = 0.0f;

    const int kn = tid >> 3;            // 0..31 (fill row)
    const int ke = (tid & 7) * 8;
    const int rmax = q0 + wrow + 15;    // warp's last (most permissive) row
    const int jmax = 4 * qt + 3;

    for (int j = 0; j <= jmax; j++) {
        const int k0 = j * 32;
        __syncthreads();   // all consumers done with Ks/Vs from previous iter

        // fill K,V tiles (tf32)
        {
            const float4* kp = (const float4*)(K + (k0 + kn) * HSn + ke);
            float4 v0 = kp[0], v1 = kp[1];
            *(uint4*)&Ks[kn][ke]     = make_uint4(f2tf(v0.x), f2tf(v0.y), f2tf(v0.z), f2tf(v0.w));
            *(uint4*)&Ks[kn][ke + 4] = make_uint4(f2tf(v1.x), f2tf(v1.y), f2tf(v1.z), f2tf(v1.w));
            const float4* vp = (const float4*)(V + (k0 + kn) * HSn + ke);
            float4 u0 = vp[0], u1 = vp[1];
            *(uint4*)&Vs[kn][ke]     = make_uint4(f2tf(u0.x), f2tf(u0.y), f2tf(u0.z), f2tf(u0.w));
            *(uint4*)&Vs[kn][ke + 4] = make_uint4(f2tf(u1.x), f2tf(u1.y), f2tf(u1.z), f2tf(u1.w));
        }
        __syncthreads();

        if (k0 > rmax) continue;   // tile fully masked for this warp's rows

        // S = Q @ K^T   (16x32; K-dim 64 -> 8 ksteps, 4 ntiles)
        float s[4][4] = {};
        #pragma unroll
        for (int ks = 0; ks < 8; ks++) {
            const int e = ks * 8 + t4;
            #pragma unroll
            for (int nt = 0; nt < 4; nt++) {
                const int n = nt * 8 + g;
                uint32_t b0 = Ks[n][e];
                uint32_t b1 = Ks[n][e + 4];
                mma_tf32(s[nt], qf[ks][0], qf[ks][1], qf[ks][2], qf[ks][3], b0, b1);
            }
        }

        // causal mask
        const int r0g = q0 + wrow + g;
        const int r1g = r0g + 8;
        #pragma unroll
        for (int nt = 0; nt < 4; nt++) {
            const int kc0 = k0 + nt * 8 + 2 * t4;
            if (kc0 > r0g)     s[nt][0] = -1e30f;
            if (kc0 + 1 > r0g) s[nt][1] = -1e30f;
            if (kc0 > r1g)     s[nt][2] = -1e30f;
            if (kc0 + 1 > r1g) s[nt][3] = -1e30f;
        }

        // online softmax: full row (32 keys) lives in this warp's quad
        float mx0 = -1e30f, mx1 = -1e30f;
        #pragma unroll
        for (int nt = 0; nt < 4; nt++) {
            mx0 = fmaxf(mx0, fmaxf(s[nt][0], s[nt][1]));
            mx1 = fmaxf(mx1, fmaxf(s[nt][2], s[nt][3]));
        }
        mx0 = fmaxf(mx0, __shfl_xor_sync(0xffffffffu, mx0, 1));
        mx0 = fmaxf(mx0, __shfl_xor_sync(0xffffffffu, mx0, 2));
        mx1 = fmaxf(mx1, __shfl_xor_sync(0xffffffffu, mx1, 1));
        mx1 = fmaxf(mx1, __shfl_xor_sync(0xffffffffu, mx1, 2));

        const float mn0 = fmaxf(m0, mx0);   // finite after j=0 (key 0 always valid)
        const float mn1 = fmaxf(m1, mx1);
        const float al0 = __expf(m0 - mn0);
        const float al1 = __expf(m1 - mn1);
        m0 = mn0; m1 = mn1;

        uint32_t pt[4][4];
        float sum0 = 0.0f, sum1 = 0.0f;
        #pragma unroll
        for (int nt = 0; nt < 4; nt++) {
            float p0 = __expf(s[nt][0] - m0);
            float p1 = __expf(s[nt][1] - m0);
            float p2 = __expf(s[nt][2] - m1);
            float p3 = __expf(s[nt][3] - m1);
            pt[nt][0] = f2tf(p0); pt[nt][1] = f2tf(p1);
            pt[nt][2] = f2tf(p2); pt[nt][3] = f2tf(p3);
            sum0 += __uint_as_float(pt[nt][0]) + __uint_as_float(pt[nt][1]);
            sum1 += __uint_as_float(pt[nt][2]) + __uint_as_float(pt[nt][3]);
        }
        sum0 += __shfl_xor_sync(0xffffffffu, sum0, 1);
        sum0 += __shfl_xor_sync(0xffffffffu, sum0, 2);
        sum1 += __shfl_xor_sync(0xffffffffu, sum1, 1);
        sum1 += __shfl_xor_sync(0xffffffffu, sum1, 2);
        l0 = l0 * al0 + sum0;
        l1 = l1 * al1 + sum1;

        // rescale running O
        #pragma unroll
        for (int nt = 0; nt < 8; nt++) {
            o[nt][0] *= al0; o[nt][1] *= al0;
            o[nt][2] *= al1; o[nt][3] *= al1;
        }

        // store P (per-warp region) in A-frag-consumable layout
        {
            const int r = wrow + g;
            #pragma unroll
            for (int nt = 0; nt < 4; nt++) {
                const int col = nt * 8 + 2 * t4;
                *(uint2*)&Ps[r][col]     = make_uint2(pt[nt][0], pt[nt][1]);
                *(uint2*)&Ps[r + 8][col] = make_uint2(pt[nt][2], pt[nt][3]);
            }
        }
        __syncwarp();

        // O += P @ V   (K-dim 32 -> 4 ksteps; 8 ntiles over HS=64)
        #pragma unroll
        for (int ks = 0; ks < 4; ks++) {
            const int k = ks * 8 + t4;
            const int r = wrow + g;
            uint32_t a0 = Ps[r][k];
            uint32_t a1 = Ps[r + 8][k];
            uint32_t a2 = Ps[r][k + 4];
            uint32_t a3 = Ps[r + 8][k + 4];
            #pragma unroll
            for (int nt = 0; nt < 8; nt++) {
                const int hs = nt * 8 + g;
                uint32_t b0 = Vs[k][hs];
                uint32_t b1 = Vs[k + 4][hs];
                mma_tf32(o[nt], a0, a1, a2, a3, b0, b1);
            }
        }
        __syncwarp();   // Ps reads done before next overwrite
    }

    // normalize + write to concat-head layout [B,S,D]
    const float inv0 = 1.0f / l0;
    const float inv1 = 1.0f / l1;
    const int row = q0 + wrow + g;
    float* Ob = g_attn + (size_t)(b * Sn) * Dn + h * HSn;
    #pragma unroll
    for (int nt = 0; nt < 8; nt++) {
        const int hs = nt * 8 + 2 * t4;
        *(float2*)&Ob[(size_t)row * Dn + hs] =
            make_float2(o[nt][0] * inv0, o[nt][1] * inv0);
        *(float2*)&Ob[(size_t)(row + 8) * Dn + hs] =
            make_float2(o[nt][2] * inv1, o[nt][3] * inv1);
    }
}

// ---------------------------------------------------------------------------
// Kernel 3: output projection via tf32 MMA. out = attn @ Wo + bo
// grid = (D/64, B*S/128), block = 256
// ---------------------------------------------------------------------------
__global__ __launch_bounds__(256) void outproj_tc(
    const float* __restrict__ Wo,
    const float* __restrict__ bo,
    float* __restrict__ out)
{
    const int nt0 = blockIdx.x * 64;
    const int mt0 = blockIdx.y * 128;
    const float* A = g_attn + (size_t)mt0 * Dn;
    const float* Bp = Wo + nt0;
    float* C = out + (size_t)mt0 * Dn + nt0;

    __shared__ uint32_t As[128][36];
    __shared__ uint32_t Bs[32][68];

    const int tid = threadIdx.x;
    const int lane = tid & 31;
    const int w = tid >> 5;
    const int wm = w >> 1;
    const int wn = w & 1;
    const int g = lane >> 2;
    const int t4 = lane & 3;

    const int ar = tid >> 1;
    const int ac = (tid & 1) * 16;
    const int bk = tid >> 3;
    const int bn = (tid & 7) * 8;

    float c[2][4][4] = {};

    for (int kc = 0; kc < Dn; kc += 32) {
        {
            const float4* src = (const float4*)(A + (size_t)ar * Dn + kc + ac);
            #pragma unroll
            for (int q = 0; q < 4; q++) {
                float4 v = src[q];
                *(uint4*)&As[ar][ac + q * 4] =
                    make_uint4(f2tf(v.x), f2tf(v.y), f2tf(v.z), f2tf(v.w));
            }
        }
        {
            const float* wp = Bp + (size_t)(kc + bk) * Dn + bn;
            float4 v0 = *(const float4*)(wp);
            float4 v1 = *(const float4*)(wp + 4);
            *(uint4*)&Bs[bk][bn]     = make_uint4(f2tf(v0.x), f2tf(v0.y), f2tf(v0.z), f2tf(v0.w));
            *(uint4*)&Bs[bk][bn + 4] = make_uint4(f2tf(v1.x), f2tf(v1.y), f2tf(v1.z), f2tf(v1.w));
        }
        __syncthreads();

        #pragma unroll
        for (int ks = 0; ks < 4; ks++) {
            uint32_t a[2][4];
            #pragma unroll
            for (int mt = 0; mt < 2; mt++) {
                const int r = wm * 32 + mt * 16 + g;
                const int k = ks * 8 + t4;
                a[mt][0] = As[r][k];
                a[mt][1] = As[r + 8][k];
                a[mt][2] = As[r][k + 4];
                a[mt][3] = As[r + 8][k + 4];
            }
            #pragma unroll
            for (int nt = 0; nt < 4; nt++) {
                const int n = wn * 32 + nt * 8 + g;
                uint32_t b0 = Bs[ks * 8 + t4][n];
                uint32_t b1 = Bs[ks * 8 + t4 + 4][n];
                mma_tf32(c[0][nt], a[0][0], a[0][1], a[0][2], a[0][3], b0, b1);
                mma_tf32(c[1][nt], a[1][0], a[1][1], a[1][2], a[1][3], b0, b1);
            }
        }
        __syncthreads();
    }

    #pragma unroll
    for (int mt = 0; mt < 2; mt++) {
        const int r = wm * 32 + mt * 16 + g;
        #pragma unroll
        for (int nt = 0; nt < 4; nt++) {
            const int n = wn * 32 + nt * 8 + 2 * t4;
            const float2 bias = *(const float2*)&bo[nt0 + n];
            *(float2*)&C[(size_t)r * Dn + n] =
                make_float2(c[mt][nt][0] + bias.x, c[mt][nt][1] + bias.y);
            *(float2*)&C[(size_t)(r + 8) * Dn + n] =
                make_float2(c[mt][nt][2] + bias.x, c[mt][nt][3] + bias.y);
        }
    }
}

// ---------------------------------------------------------------------------
extern "C" void kernel_launch(void* const* d_in, const int* in_sizes, int n_in,
                              void* d_out, int out_size)
{
    const float* X  = (const float*)d_in[0];   // [B,S,D]
    const float* Wq = (const float*)d_in[1];   // [H,D,HS]
    const float* Wk = (const float*)d_in[2];
    const float* Wv = (const float*)d_in[3];
    const float* Wo = (const float*)d_in[4];   // [D,D]
    const float* bo = (const float*)d_in[5];   // [D]
    float* out = (float*)d_out;                // [B,S,D]

    proj_tc<<<dim3(Sn / 128, Bn * Hn, 3), 256>>>(X, Wq, Wk, Wv);
    attn_tc<<<dim3(Sn / 128, Bn * Hn), 256>>>();
    outproj_tc<<<dim3(Dn / 64, (Bn * Sn) / 128), 256>>>(Wo, bo, out);
}

// round 4
// speedup vs baseline: 3.0109x; 1.1724x over previous
#include <cuda_runtime.h>
#include <cstdint>

// Problem constants
constexpr int Bn = 4;
constexpr int Sn = 2048;
constexpr int Dn = 1024;
constexpr int Hn = 16;
constexpr int HSn = 64;     // head size

// Scratch: Q,K,V in [B,H,S,HS], attention output in [B,S,D]
__device__ float g_q[Bn * Hn * Sn * HSn];
__device__ float g_k[Bn * Hn * Sn * HSn];
__device__ float g_v[Bn * Hn * Sn * HSn];
__device__ float g_attn[Bn * Sn * Dn];

// ---------------------------------------------------------------------------
// tf32 helpers
// ---------------------------------------------------------------------------
__device__ __forceinline__ uint32_t f2tf(float x) {
    uint32_t r;
    asm("cvt.rna.tf32.f32 %0, %1;" : "=r"(r) : "f"(x));
    return r;
}

__device__ __forceinline__ void mma_tf32(float c[4],
                                         uint32_t a0, uint32_t a1, uint32_t a2, uint32_t a3,
                                         uint32_t b0, uint32_t b1) {
    asm volatile(
        "mma.sync.aligned.m16n8k8.row.col.f32.tf32.tf32.f32 "
        "{%0,%1,%2,%3}, {%4,%5,%6,%7}, {%8,%9}, {%0,%1,%2,%3};\n"
        : "+f"(c[0]), "+f"(c[1]), "+f"(c[2]), "+f"(c[3])
        : "r"(a0), "r"(a1), "r"(a2), "r"(a3), "r"(b0), "r"(b1));
}

// ---------------------------------------------------------------------------
// Kernel 1: merged QKV projection GEMM.
// N-space = which(3) x head(16) x 64. Block tile 128(M) x 128(N) = 2 heads.
// 8 warps (4 wm x 2 wn), warp tile 32x64. K chunk 16, double-buffered smem.
// grid = (24, B*S/128), block = 256
// ---------------------------------------------------------------------------
__global__ __launch_bounds__(256) void proj_tc(
    const float* __restrict__ X,
    const float* __restrict__ Wq,
    const float* __restrict__ Wk,
    const float* __restrict__ Wv)
{
    const int xx = blockIdx.x;            // 0..23
    const int which = xx >> 3;            // 0=q 1=k 2=v
    const int h0 = (xx & 7) * 2;          // first head of the pair
    const int m0 = blockIdx.y * 128;      // row in [B*S]
    const int b = m0 >> 11;
    const int s0 = m0 & 2047;

    const float* W;
    float* outb;
    if (which == 0)      { W = Wq; outb = g_q; }
    else if (which == 1) { W = Wk; outb = g_k; }
    else                 { W = Wv; outb = g_v; }

    const float* A = X + (size_t)m0 * Dn;
    const float* B0 = W + (size_t)h0 * Dn * HSn;   // head h0 weight block

    __shared__ uint32_t As[2][128][20];   // [m][k], frag banks 20g+t4 (perfect)
    __shared__ uint32_t Bs[2][16][136];   // [k][n], frag banks 8t4+g (perfect)

    const int tid = threadIdx.x;
    const int lane = tid & 31;
    const int w = tid >> 5;
    const int wm = w >> 1;     // 0..3
    const int wn = w & 1;      // 0..1
    const int g = lane >> 2;
    const int t4 = lane & 3;

    // fill mappings
    const int ar = tid >> 1;             // 0..127
    const int ac = (tid & 1) * 8;        // 0 or 8
    const int bk = tid >> 4;             // 0..15
    const int bn = (tid & 15) * 8;       // 0..120
    // per-thread B source (head split at column 64; 8-col groups never straddle)
    const float* Bsrc = B0 + (bn < 64 ? bn : (size_t)Dn * HSn + (bn - 64));
    const float* Arow = A + (size_t)ar * Dn + ac;

    float c[2][8][4] = {};

    // prime buffer 0 with chunk 0
    {
        float4 a0 = *(const float4*)(Arow);
        float4 a1 = *(const float4*)(Arow + 4);
        float4 b0 = *(const float4*)(Bsrc + bk * HSn);
        float4 b1 = *(const float4*)(Bsrc + bk * HSn + 4);
        *(uint4*)&As[0][ar][ac]     = make_uint4(f2tf(a0.x), f2tf(a0.y), f2tf(a0.z), f2tf(a0.w));
        *(uint4*)&As[0][ar][ac + 4] = make_uint4(f2tf(a1.x), f2tf(a1.y), f2tf(a1.z), f2tf(a1.w));
        *(uint4*)&Bs[0][bk][bn]     = make_uint4(f2tf(b0.x), f2tf(b0.y), f2tf(b0.z), f2tf(b0.w));
        *(uint4*)&Bs[0][bk][bn + 4] = make_uint4(f2tf(b1.x), f2tf(b1.y), f2tf(b1.z), f2tf(b1.w));
    }
    __syncthreads();

    int buf = 0;
    for (int ch = 0; ch < 64; ch++) {
        float4 pa0, pa1, pb0, pb1;
        const bool more = (ch + 1 < 64);
        if (more) {
            const int kc = (ch + 1) * 16;
            pa0 = *(const float4*)(Arow + kc);
            pa1 = *(const float4*)(Arow + kc + 4);
            pb0 = *(const float4*)(Bsrc + (kc + bk) * HSn);
            pb1 = *(const float4*)(Bsrc + (kc + bk) * HSn + 4);
        }

        // compute current chunk (2 ksteps)
        #pragma unroll
        for (int ks = 0; ks < 2; ks++) {
            const int k = ks * 8 + t4;
            uint32_t a[2][4];
            #pragma unroll
            for (int mt = 0; mt < 2; mt++) {
                const int r = wm * 32 + mt * 16 + g;
                a[mt][0] = As[buf][r][k];
                a[mt][1] = As[buf][r + 8][k];
                a[mt][2] = As[buf][r][k + 4];
                a[mt][3] = As[buf][r + 8][k + 4];
            }
            #pragma unroll
            for (int nt = 0; nt < 8; nt++) {
                const int n = wn * 64 + nt * 8 + g;
                uint32_t b0 = Bs[buf][k][n];
                uint32_t b1 = Bs[buf][k + 4][n];
                mma_tf32(c[0][nt], a[0][0], a[0][1], a[0][2], a[0][3], b0, b1);
                mma_tf32(c[1][nt], a[1][0], a[1][1], a[1][2], a[1][3], b0, b1);
            }
        }

        if (more) {
            const int nb = buf ^ 1;
            *(uint4*)&As[nb][ar][ac]     = make_uint4(f2tf(pa0.x), f2tf(pa0.y), f2tf(pa0.z), f2tf(pa0.w));
            *(uint4*)&As[nb][ar][ac + 4] = make_uint4(f2tf(pa1.x), f2tf(pa1.y), f2tf(pa1.z), f2tf(pa1.w));
            *(uint4*)&Bs[nb][bk][bn]     = make_uint4(f2tf(pb0.x), f2tf(pb0.y), f2tf(pb0.z), f2tf(pb0.w));
            *(uint4*)&Bs[nb][bk][bn + 4] = make_uint4(f2tf(pb1.x), f2tf(pb1.y), f2tf(pb1.z), f2tf(pb1.w));
        }
        __syncthreads();
        buf ^= 1;
    }

    // epilogue: head = h0 + wn, local col = nt*8 + 2*t4
    float* O = outb + ((size_t)(b * Hn + h0 + wn) * Sn + s0) * HSn;
    #pragma unroll
    for (int mt = 0; mt < 2; mt++) {
        const int r = wm * 32 + mt * 16 + g;
        #pragma unroll
        for (int nt = 0; nt < 8; nt++) {
            const int hs = nt * 8 + 2 * t4;
            *(float2*)&O[(size_t)r * HSn + hs]       = make_float2(c[0 + 0][nt][0], c[mt][nt][0]), // placeholder avoided below
            *(float2*)&O[(size_t)r * HSn + hs]       = make_float2(c[mt][nt][0], c[mt][nt][1]);
            *(float2*)&O[(size_t)(r + 8) * HSn + hs] = make_float2(c[mt][nt][2], c[mt][nt][3]);
        }
    }
}

// ---------------------------------------------------------------------------
// Kernel 2: causal flash attention via tf32 MMA (unchanged from R3 pass).
// BM=128 queries, BN=32 keys. 8 warps stacked along M (16 rows each).
// grid = (S/128, B*H), block = 256
// ---------------------------------------------------------------------------
__global__ __launch_bounds__(256) void attn_tc()
{
    const int qt = blockIdx.x;
    const int bh = blockIdx.y;
    const int b = bh >> 4;
    const int h = bh & 15;
    const int q0 = qt * 128;

    const float* Q = g_q + (bh * Sn + q0) * HSn;
    const float* K = g_k + bh * Sn * HSn;
    const float* V = g_v + bh * Sn * HSn;

    __shared__ uint32_t Ks[32][68];
    __shared__ uint32_t Vs[32][72];
    __shared__ uint32_t Ps[128][36];

    const int tid = threadIdx.x;
    const int lane = tid & 31;
    const int w = tid >> 5;
    const int g = lane >> 2;
    const int t4 = lane & 3;
    const int wrow = w * 16;

    uint32_t qf[8][4];
    {
        const float* Qw = Q + (wrow + g) * HSn;
        #pragma unroll
        for (int ks = 0; ks < 8; ks++) {
            const int e = ks * 8 + t4;
            qf[ks][0] = f2tf(Qw[e] * 0.125f);
            qf[ks][1] = f2tf(Qw[8 * HSn + e] * 0.125f);
            qf[ks][2] = f2tf(Qw[e + 4] * 0.125f);
            qf[ks][3] = f2tf(Qw[8 * HSn + e + 4] * 0.125f);
        }
    }

    float o[8][4] = {};
    float m0 = -1e30f, m1 = -1e30f, l0 = 0.0f, l1 = 0.0f;

    const int kn = tid >> 3;
    const int ke = (tid & 7) * 8;
    const int rmax = q0 + wrow + 15;
    const int jmax = 4 * qt + 3;

    for (int j = 0; j <= jmax; j++) {
        const int k0 = j * 32;
        __syncthreads();

        {
            const float4* kp = (const float4*)(K + (k0 + kn) * HSn + ke);
            float4 v0 = kp[0], v1 = kp[1];
            *(uint4*)&Ks[kn][ke]     = make_uint4(f2tf(v0.x), f2tf(v0.y), f2tf(v0.z), f2tf(v0.w));
            *(uint4*)&Ks[kn][ke + 4] = make_uint4(f2tf(v1.x), f2tf(v1.y), f2tf(v1.z), f2tf(v1.w));
            const float4* vp = (const float4*)(V + (k0 + kn) * HSn + ke);
            float4 u0 = vp[0], u1 = vp[1];
            *(uint4*)&Vs[kn][ke]     = make_uint4(f2tf(u0.x), f2tf(u0.y), f2tf(u0.z), f2tf(u0.w));
            *(uint4*)&Vs[kn][ke + 4] = make_uint4(f2tf(u1.x), f2tf(u1.y), f2tf(u1.z), f2tf(u1.w));
        }
        __syncthreads();

        if (k0 > rmax) continue;

        float s[4][4] = {};
        #pragma unroll
        for (int ks = 0; ks < 8; ks++) {
            const int e = ks * 8 + t4;
            #pragma unroll
            for (int nt = 0; nt < 4; nt++) {
                const int n = nt * 8 + g;
                uint32_t b0 = Ks[n][e];
                uint32_t b1 = Ks[n][e + 4];
                mma_tf32(s[nt], qf[ks][0], qf[ks][1], qf[ks][2], qf[ks][3], b0, b1);
            }
        }

        const int r0g = q0 + wrow + g;
        const int r1g = r0g + 8;
        #pragma unroll
        for (int nt = 0; nt < 4; nt++) {
            const int kc0 = k0 + nt * 8 + 2 * t4;
            if (kc0 > r0g)     s[nt][0] = -1e30f;
            if (kc0 + 1 > r0g) s[nt][1] = -1e30f;
            if (kc0 > r1g)     s[nt][2] = -1e30f;
            if (kc0 + 1 > r1g) s[nt][3] = -1e30f;
        }

        float mx0 = -1e30f, mx1 = -1e30f;
        #pragma unroll
        for (int nt = 0; nt < 4; nt++) {
            mx0 = fmaxf(mx0, fmaxf(s[nt][0], s[nt][1]));
            mx1 = fmaxf(mx1, fmaxf(s[nt][2], s[nt][3]));
        }
        mx0 = fmaxf(mx0, __shfl_xor_sync(0xffffffffu, mx0, 1));
        mx0 = fmaxf(mx0, __shfl_xor_sync(0xffffffffu, mx0, 2));
        mx1 = fmaxf(mx1, __shfl_xor_sync(0xffffffffu, mx1, 1));
        mx1 = fmaxf(mx1, __shfl_xor_sync(0xffffffffu, mx1, 2));

        const float mn0 = fmaxf(m0, mx0);
        const float mn1 = fmaxf(m1, mx1);
        const float al0 = __expf(m0 - mn0);
        const float al1 = __expf(m1 - mn1);
        m0 = mn0; m1 = mn1;

        uint32_t pt[4][4];
        float sum0 = 0.0f, sum1 = 0.0f;
        #pragma unroll
        for (int nt = 0; nt < 4; nt++) {
            float p0 = __expf(s[nt][0] - m0);
            float p1 = __expf(s[nt][1] - m0);
            float p2 = __expf(s[nt][2] - m1);
            float p3 = __expf(s[nt][3] - m1);
            pt[nt][0] = f2tf(p0); pt[nt][1] = f2tf(p1);
            pt[nt][2] = f2tf(p2); pt[nt][3] = f2tf(p3);
            sum0 += __uint_as_float(pt[nt][0]) + __uint_as_float(pt[nt][1]);
            sum1 += __uint_as_float(pt[nt][2]) + __uint_as_float(pt[nt][3]);
        }
        sum0 += __shfl_xor_sync(0xffffffffu, sum0, 1);
        sum0 += __shfl_xor_sync(0xffffffffu, sum0, 2);
        sum1 += __shfl_xor_sync(0xffffffffu, sum1, 1);
        sum1 += __shfl_xor_sync(0xffffffffu, sum1, 2);
        l0 = l0 * al0 + sum0;
        l1 = l1 * al1 + sum1;

        #pragma unroll
        for (int nt = 0; nt < 8; nt++) {
            o[nt][0] *= al0; o[nt][1] *= al0;
            o[nt][2] *= al1; o[nt][3] *= al1;
        }

        {
            const int r = wrow + g;
            #pragma unroll
            for (int nt = 0; nt < 4; nt++) {
                const int col = nt * 8 + 2 * t4;
                *(uint2*)&Ps[r][col]     = make_uint2(pt[nt][0], pt[nt][1]);
                *(uint2*)&Ps[r + 8][col] = make_uint2(pt[nt][2], pt[nt][3]);
            }
        }
        __syncwarp();

        #pragma unroll
        for (int ks = 0; ks < 4; ks++) {
            const int k = ks * 8 + t4;
            const int r = wrow + g;
            uint32_t a0 = Ps[r][k];
            uint32_t a1 = Ps[r + 8][k];
            uint32_t a2 = Ps[r][k + 4];
            uint32_t a3 = Ps[r + 8][k + 4];
            #pragma unroll
            for (int nt = 0; nt < 8; nt++) {
                const int hs = nt * 8 + g;
                uint32_t b0 = Vs[k][hs];
                uint32_t b1 = Vs[k + 4][hs];
                mma_tf32(o[nt], a0, a1, a2, a3, b0, b1);
            }
        }
        __syncwarp();
    }

    const float inv0 = 1.0f / l0;
    const float inv1 = 1.0f / l1;
    const int row = q0 + wrow + g;
    float* Ob = g_attn + (size_t)(b * Sn) * Dn + h * HSn;
    #pragma unroll
    for (int nt = 0; nt < 8; nt++) {
        const int hs = nt * 8 + 2 * t4;
        *(float2*)&Ob[(size_t)row * Dn + hs] =
            make_float2(o[nt][0] * inv0, o[nt][1] * inv0);
        *(float2*)&Ob[(size_t)(row + 8) * Dn + hs] =
            make_float2(o[nt][2] * inv1, o[nt][3] * inv1);
    }
}

// ---------------------------------------------------------------------------
// Kernel 3: output projection. Same 128x128 double-buffered template.
// grid = (D/128, B*S/128), block = 256
// ---------------------------------------------------------------------------
__global__ __launch_bounds__(256) void outproj_tc(
    const float* __restrict__ Wo,
    const float* __restrict__ bo,
    float* __restrict__ out)
{
    const int nt0 = blockIdx.x * 128;
    const int m0 = blockIdx.y * 128;
    const float* A = g_attn + (size_t)m0 * Dn;

    __shared__ uint32_t As[2][128][20];
    __shared__ uint32_t Bs[2][16][136];

    const int tid = threadIdx.x;
    const int lane = tid & 31;
    const int w = tid >> 5;
    const int wm = w >> 1;
    const int wn = w & 1;
    const int g = lane >> 2;
    const int t4 = lane & 3;

    const int ar = tid >> 1;
    const int ac = (tid & 1) * 8;
    const int bk = tid >> 4;
    const int bn = (tid & 15) * 8;
    const float* Arow = A + (size_t)ar * Dn + ac;
    const float* Bsrc = Wo + nt0 + bn;

    float c[2][8][4] = {};

    {
        float4 a0 = *(const float4*)(Arow);
        float4 a1 = *(const float4*)(Arow + 4);
        float4 b0 = *(const float4*)(Bsrc + (size_t)bk * Dn);
        float4 b1 = *(const float4*)(Bsrc + (size_t)bk * Dn + 4);
        *(uint4*)&As[0][ar][ac]     = make_uint4(f2tf(a0.x), f2tf(a0.y), f2tf(a0.z), f2tf(a0.w));
        *(uint4*)&As[0][ar][ac + 4] = make_uint4(f2tf(a1.x), f2tf(a1.y), f2tf(a1.z), f2tf(a1.w));
        *(uint4*)&Bs[0][bk][bn]     = make_uint4(f2tf(b0.x), f2tf(b0.y), f2tf(b0.z), f2tf(b0.w));
        *(uint4*)&Bs[0][bk][bn + 4] = make_uint4(f2tf(b1.x), f2tf(b1.y), f2tf(b1.z), f2tf(b1.w));
    }
    __syncthreads();

    int buf = 0;
    for (int ch = 0; ch < 64; ch++) {
        float4 pa0, pa1, pb0, pb1;
        const bool more = (ch + 1 < 64);
        if (more) {
            const int kc = (ch + 1) * 16;
            pa0 = *(const float4*)(Arow + kc);
            pa1 = *(const float4*)(Arow + kc + 4);
            pb0 = *(const float4*)(Bsrc + (size_t)(kc + bk) * Dn);
            pb1 = *(const float4*)(Bsrc + (size_t)(kc + bk) * Dn + 4);
        }

        #pragma unroll
        for (int ks = 0; ks < 2; ks++) {
            const int k = ks * 8 + t4;
            uint32_t a[2][4];
            #pragma unroll
            for (int mt = 0; mt < 2; mt++) {
                const int r = wm * 32 + mt * 16 + g;
                a[mt][0] = As[buf][r][k];
                a[mt][1] = As[buf][r + 8][k];
                a[mt][2] = As[buf][r][k + 4];
                a[mt][3] = As[buf][r + 8][k + 4];
            }
            #pragma unroll
            for (int nt = 0; nt < 8; nt++) {
                const int n = wn * 64 + nt * 8 + g;
                uint32_t b0 = Bs[buf][k][n];
                uint32_t b1 = Bs[buf][k + 4][n];
                mma_tf32(c[0][nt], a[0][0], a[0][1], a[0][2], a[0][3], b0, b1);
                mma_tf32(c[1][nt], a[1][0], a[1][1], a[1][2], a[1][3], b0, b1);
            }
        }

        if (more) {
            const int nb = buf ^ 1;
            *(uint4*)&As[nb][ar][ac]     = make_uint4(f2tf(pa0.x), f2tf(pa0.y), f2tf(pa0.z), f2tf(pa0.w));
            *(uint4*)&As[nb][ar][ac + 4] = make_uint4(f2tf(pa1.x), f2tf(pa1.y), f2tf(pa1.z), f2tf(pa1.w));
            *(uint4*)&Bs[nb][bk][bn]     = make_uint4(f2tf(pb0.x), f2tf(pb0.y), f2tf(pb0.z), f2tf(pb0.w));
            *(uint4*)&Bs[nb][bk][bn + 4] = make_uint4(f2tf(pb1.x), f2tf(pb1.y), f2tf(pb1.z), f2tf(pb1.w));
        }
        __syncthreads();
        buf ^= 1;
    }

    float* C = out + (size_t)m0 * Dn + nt0;
    #pragma unroll
    for (int mt = 0; mt < 2; mt++) {
        const int r = wm * 32 + mt * 16 + g;
        #pragma unroll
        for (int nt = 0; nt < 8; nt++) {
            const int n = wn * 64 + nt * 8 + 2 * t4;
            const float2 bias = *(const float2*)&bo[nt0 + n];
            *(float2*)&C[(size_t)r * Dn + n] =
                make_float2(c[mt][nt][0] + bias.x, c[mt][nt][1] + bias.y);
            *(float2*)&C[(size_t)(r + 8) * Dn + n] =
                make_float2(c[mt][nt][2] + bias.x, c[mt][nt][3] + bias.y);
        }
    }
}

// ---------------------------------------------------------------------------
extern "C" void kernel_launch(void* const* d_in, const int* in_sizes, int n_in,
                              void* d_out, int out_size)
{
    const float* X  = (const float*)d_in[0];
    const float* Wq = (const float*)d_in[1];
    const float* Wk = (const float*)d_in[2];
    const float* Wv = (const float*)d_in[3];
    const float* Wo = (const float*)d_in[4];
    const float* bo = (const float*)d_in[5];
    float* out = (float*)d_out;

    proj_tc<<<dim3(24, (Bn * Sn) / 128), 256>>>(X, Wq, Wk, Wv);
    attn_tc<<<dim3(Sn / 128, Bn * Hn), 256>>>();
    outproj_tc<<<dim3(Dn / 128, (Bn * Sn) / 128), 256>>>(Wo, bo, out);
}

// round 5
// speedup vs baseline: 3.2901x; 1.0927x over previous
#include <cuda_runtime.h>
#include <cstdint>

// Problem constants
constexpr int Bn = 4;
constexpr int Sn = 2048;
constexpr int Dn = 1024;
constexpr int Hn = 16;
constexpr int HSn = 64;     // head size

constexpr int WSZ = Hn * Dn * HSn;         // one projection weight: 1M elems

// Scratch. g_q/g_k/g_v/g_attn hold tf32 BIT PATTERNS (as uint32).
__device__ uint32_t g_q[Bn * Hn * Sn * HSn];
__device__ uint32_t g_k[Bn * Hn * Sn * HSn];
__device__ uint32_t g_v[Bn * Hn * Sn * HSn];
__device__ uint32_t g_attn[Bn * Sn * Dn];
__device__ uint32_t g_xt[Bn * Sn * Dn];    // X converted to tf32
__device__ uint32_t g_wt[3 * WSZ];         // Wq|Wk|Wv converted
__device__ uint32_t g_wot[Dn * Dn];        // Wo converted

// ---------------------------------------------------------------------------
// helpers
// ---------------------------------------------------------------------------
__device__ __forceinline__ uint32_t f2tf(float x) {
    uint32_t r;
    asm("cvt.rna.tf32.f32 %0, %1;" : "=r"(r) : "f"(x));
    return r;
}

__device__ __forceinline__ void mma_tf32(float c[4],
                                         uint32_t a0, uint32_t a1, uint32_t a2, uint32_t a3,
                                         uint32_t b0, uint32_t b1) {
    asm volatile(
        "mma.sync.aligned.m16n8k8.row.col.f32.tf32.tf32.f32 "
        "{%0,%1,%2,%3}, {%4,%5,%6,%7}, {%8,%9}, {%0,%1,%2,%3};\n"
        : "+f"(c[0]), "+f"(c[1]), "+f"(c[2]), "+f"(c[3])
        : "r"(a0), "r"(a1), "r"(a2), "r"(a3), "r"(b0), "r"(b1));
}

__device__ __forceinline__ void cp16(void* smem_dst, const void* gmem_src) {
    uint32_t d = (uint32_t)__cvta_generic_to_shared(smem_dst);
    asm volatile("cp.async.ca.shared.global [%0], [%1], 16;\n"
                 :: "r"(d), "l"(gmem_src));
}
#define CP_COMMIT() asm volatile("cp.async.commit_group;\n" ::: "memory")
#define CP_WAIT0()  asm volatile("cp.async.wait_group 0;\n" ::: "memory")

// ---------------------------------------------------------------------------
// Kernel 0: elementwise fp32 -> tf32 bits
// ---------------------------------------------------------------------------
__global__ __launch_bounds__(256) void cvt_tf32(
    const float4* __restrict__ src, uint4* __restrict__ dst, int n4)
{
    int i = blockIdx.x * blockDim.x + threadIdx.x;
    int stride = gridDim.x * blockDim.x;
    for (; i < n4; i += stride) {
        float4 v = src[i];
        dst[i] = make_uint4(f2tf(v.x), f2tf(v.y), f2tf(v.z), f2tf(v.w));
    }
}

// ---------------------------------------------------------------------------
// Kernel 1: merged QKV projection GEMM (cvt-free, cp.async double-buffered).
// Block tile 128x128 (2 heads). 8 warps (4x2), warp tile 32x64. K chunk 16.
// grid = (24, B*S/128), block = 256
// Q outputs are pre-scaled by 0.125 and tf32-rounded; K/V tf32-rounded.
// ---------------------------------------------------------------------------
__global__ __launch_bounds__(256) void proj_tc()
{
    const int xx = blockIdx.x;            // 0..23
    const int which = xx >> 3;            // 0=q 1=k 2=v
    const int h0 = (xx & 7) * 2;          // first head of the pair
    const int m0 = blockIdx.y * 128;      // row in [B*S]
    const int b = m0 >> 11;
    const int s0 = m0 & 2047;

    uint32_t* outb = (which == 0) ? g_q : (which == 1) ? g_k : g_v;
    const uint32_t* A = g_xt + (size_t)m0 * Dn;
    const uint32_t* B0 = g_wt + (size_t)which * WSZ + (size_t)h0 * Dn * HSn;

    __shared__ uint32_t As[2][128][20];   // frag banks 20g+t4 -> 4g+t4 (perfect)
    __shared__ uint32_t Bs[2][16][136];   // frag banks 8t4+g (perfect)

    const int tid = threadIdx.x;
    const int lane = tid & 31;
    const int w = tid >> 5;
    const int wm = w >> 1;
    const int wn = w & 1;
    const int g = lane >> 2;
    const int t4 = lane & 3;

    const int ar = tid >> 1;             // 0..127
    const int ac = (tid & 1) * 8;        // 0 or 8
    const int bk = tid >> 4;             // 0..15
    const int bn = (tid & 15) * 8;       // 0..120
    const uint32_t* Bsrc = B0 + (bn < 64 ? bn : (size_t)Dn * HSn + (bn - 64));
    const uint32_t* Arow = A + (size_t)ar * Dn + ac;

    float c[2][8][4] = {};

    // prime stage 0 with chunk 0
    cp16(&As[0][ar][ac],     Arow);
    cp16(&As[0][ar][ac + 4], Arow + 4);
    cp16(&Bs[0][bk][bn],     Bsrc + bk * HSn);
    cp16(&Bs[0][bk][bn + 4], Bsrc + bk * HSn + 4);
    CP_COMMIT();
    CP_WAIT0();
    __syncthreads();

    int buf = 0;
    for (int ch = 0; ch < 64; ch++) {
        const bool more = (ch + 1 < 64);
        if (more) {
            const int kc = (ch + 1) * 16;
            const int nb = buf ^ 1;
            cp16(&As[nb][ar][ac],     Arow + kc);
            cp16(&As[nb][ar][ac + 4], Arow + kc + 4);
            cp16(&Bs[nb][bk][bn],     Bsrc + (kc + bk) * HSn);
            cp16(&Bs[nb][bk][bn + 4], Bsrc + (kc + bk) * HSn + 4);
            CP_COMMIT();
        }

        #pragma unroll
        for (int ks = 0; ks < 2; ks++) {
            const int k = ks * 8 + t4;
            uint32_t a[2][4];
            #pragma unroll
            for (int mt = 0; mt < 2; mt++) {
                const int r = wm * 32 + mt * 16 + g;
                a[mt][0] = As[buf][r][k];
                a[mt][1] = As[buf][r + 8][k];
                a[mt][2] = As[buf][r][k + 4];
                a[mt][3] = As[buf][r + 8][k + 4];
            }
            #pragma unroll
            for (int nt = 0; nt < 8; nt++) {
                const int n = wn * 64 + nt * 8 + g;
                uint32_t b0 = Bs[buf][k][n];
                uint32_t b1 = Bs[buf][k + 4][n];
                mma_tf32(c[0][nt], a[0][0], a[0][1], a[0][2], a[0][3], b0, b1);
                mma_tf32(c[1][nt], a[1][0], a[1][1], a[1][2], a[1][3], b0, b1);
            }
        }

        if (more) CP_WAIT0();
        __syncthreads();
        buf ^= 1;
    }

    // epilogue: head = h0 + wn; Q pre-scaled by 0.125; all tf32-rounded bits
    const float sc = (which == 0) ? 0.125f : 1.0f;
    uint32_t* O = outb + ((size_t)(b * Hn + h0 + wn) * Sn + s0) * HSn;
    #pragma unroll
    for (int mt = 0; mt < 2; mt++) {
        const int r = wm * 32 + mt * 16 + g;
        #pragma unroll
        for (int nt = 0; nt < 8; nt++) {
            const int hs = nt * 8 + 2 * t4;
            *(uint2*)&O[(size_t)r * HSn + hs] =
                make_uint2(f2tf(c[mt][nt][0] * sc), f2tf(c[mt][nt][1] * sc));
            *(uint2*)&O[(size_t)(r + 8) * HSn + hs] =
                make_uint2(f2tf(c[mt][nt][2] * sc), f2tf(c[mt][nt][3] * sc));
        }
    }
}

// ---------------------------------------------------------------------------
// Kernel 2: causal flash attention. BM=128, BN=32, 8 warps along M.
// Q/K/V already tf32 bits (Q pre-scaled). Output written tf32-rounded.
// grid = (S/128, B*H), block = 256
// ---------------------------------------------------------------------------
__global__ __launch_bounds__(256) void attn_tc()
{
    const int qt = blockIdx.x;
    const int bh = blockIdx.y;
    const int b = bh >> 4;
    const int h = bh & 15;
    const int q0 = qt * 128;

    const uint32_t* Q = g_q + (size_t)(bh * Sn + q0) * HSn;
    const uint32_t* K = g_k + (size_t)bh * Sn * HSn;
    const uint32_t* V = g_v + (size_t)bh * Sn * HSn;

    __shared__ uint32_t Ks[32][68];
    __shared__ uint32_t Vs[32][72];
    __shared__ uint32_t Ps[128][36];

    const int tid = threadIdx.x;
    const int lane = tid & 31;
    const int w = tid >> 5;
    const int g = lane >> 2;
    const int t4 = lane & 3;
    const int wrow = w * 16;

    // Q fragments: direct bit loads
    uint32_t qf[8][4];
    {
        const uint32_t* Qw = Q + (size_t)(wrow + g) * HSn;
        #pragma unroll
        for (int ks = 0; ks < 8; ks++) {
            const int e = ks * 8 + t4;
            qf[ks][0] = Qw[e];
            qf[ks][1] = Qw[8 * HSn + e];
            qf[ks][2] = Qw[e + 4];
            qf[ks][3] = Qw[8 * HSn + e + 4];
        }
    }

    float o[8][4] = {};
    float m0 = -1e30f, m1 = -1e30f, l0 = 0.0f, l1 = 0.0f;

    const int kn = tid >> 3;            // 0..31
    const int ke = (tid & 7) * 8;
    const int rmax = q0 + wrow + 15;
    const int jmax = 4 * qt + 3;

    for (int j = 0; j <= jmax; j++) {
        const int k0 = j * 32;
        __syncthreads();   // consumers done with Ks/Vs

        // fill K,V via cp.async (no cvt, no register round-trip)
        cp16(&Ks[kn][ke],     K + (size_t)(k0 + kn) * HSn + ke);
        cp16(&Ks[kn][ke + 4], K + (size_t)(k0 + kn) * HSn + ke + 4);
        cp16(&Vs[kn][ke],     V + (size_t)(k0 + kn) * HSn + ke);
        cp16(&Vs[kn][ke + 4], V + (size_t)(k0 + kn) * HSn + ke + 4);
        CP_COMMIT();
        CP_WAIT0();
        __syncthreads();

        if (k0 > rmax) continue;

        // S = Q @ K^T
        float s[4][4] = {};
        #pragma unroll
        for (int ks = 0; ks < 8; ks++) {
            const int e = ks * 8 + t4;
            #pragma unroll
            for (int nt = 0; nt < 4; nt++) {
                const int n = nt * 8 + g;
                uint32_t b0 = Ks[n][e];
                uint32_t b1 = Ks[n][e + 4];
                mma_tf32(s[nt], qf[ks][0], qf[ks][1], qf[ks][2], qf[ks][3], b0, b1);
            }
        }

        // causal mask
        const int r0g = q0 + wrow + g;
        const int r1g = r0g + 8;
        #pragma unroll
        for (int nt = 0; nt < 4; nt++) {
            const int kc0 = k0 + nt * 8 + 2 * t4;
            if (kc0 > r0g)     s[nt][0] = -1e30f;
            if (kc0 + 1 > r0g) s[nt][1] = -1e30f;
            if (kc0 > r1g)     s[nt][2] = -1e30f;
            if (kc0 + 1 > r1g) s[nt][3] = -1e30f;
        }

        // online softmax (warp-local rows)
        float mx0 = -1e30f, mx1 = -1e30f;
        #pragma unroll
        for (int nt = 0; nt < 4; nt++) {
            mx0 = fmaxf(mx0, fmaxf(s[nt][0], s[nt][1]));
            mx1 = fmaxf(mx1, fmaxf(s[nt][2], s[nt][3]));
        }
        mx0 = fmaxf(mx0, __shfl_xor_sync(0xffffffffu, mx0, 1));
        mx0 = fmaxf(mx0, __shfl_xor_sync(0xffffffffu, mx0, 2));
        mx1 = fmaxf(mx1, __shfl_xor_sync(0xffffffffu, mx1, 1));
        mx1 = fmaxf(mx1, __shfl_xor_sync(0xffffffffu, mx1, 2));

        const float mn0 = fmaxf(m0, mx0);
        const float mn1 = fmaxf(m1, mx1);
        const float al0 = __expf(m0 - mn0);
        const float al1 = __expf(m1 - mn1);
        m0 = mn0; m1 = mn1;

        uint32_t pt[4][4];
        float sum0 = 0.0f, sum1 = 0.0f;
        #pragma unroll
        for (int nt = 0; nt < 4; nt++) {
            float p0 = __expf(s[nt][0] - m0);
            float p1 = __expf(s[nt][1] - m0);
            float p2 = __expf(s[nt][2] - m1);
            float p3 = __expf(s[nt][3] - m1);
            pt[nt][0] = f2tf(p0); pt[nt][1] = f2tf(p1);
            pt[nt][2] = f2tf(p2); pt[nt][3] = f2tf(p3);
            sum0 += __uint_as_float(pt[nt][0]) + __uint_as_float(pt[nt][1]);
            sum1 += __uint_as_float(pt[nt][2]) + __uint_as_float(pt[nt][3]);
        }
        sum0 += __shfl_xor_sync(0xffffffffu, sum0, 1);
        sum0 += __shfl_xor_sync(0xffffffffu, sum0, 2);
        sum1 += __shfl_xor_sync(0xffffffffu, sum1, 1);
        sum1 += __shfl_xor_sync(0xffffffffu, sum1, 2);
        l0 = l0 * al0 + sum0;
        l1 = l1 * al1 + sum1;

        #pragma unroll
        for (int nt = 0; nt < 8; nt++) {
            o[nt][0] *= al0; o[nt][1] *= al0;
            o[nt][2] *= al1; o[nt][3] *= al1;
        }

        // P -> per-warp smem (A-frag layout)
        {
            const int r = wrow + g;
            #pragma unroll
            for (int nt = 0; nt < 4; nt++) {
                const int col = nt * 8 + 2 * t4;
                *(uint2*)&Ps[r][col]     = make_uint2(pt[nt][0], pt[nt][1]);
                *(uint2*)&Ps[r + 8][col] = make_uint2(pt[nt][2], pt[nt][3]);
            }
        }
        __syncwarp();

        // O += P @ V
        #pragma unroll
        for (int ks = 0; ks < 4; ks++) {
            const int k = ks * 8 + t4;
            const int r = wrow + g;
            uint32_t a0 = Ps[r][k];
            uint32_t a1 = Ps[r + 8][k];
            uint32_t a2 = Ps[r][k + 4];
            uint32_t a3 = Ps[r + 8][k + 4];
            #pragma unroll
            for (int nt = 0; nt < 8; nt++) {
                const int hs = nt * 8 + g;
                uint32_t b0 = Vs[k][hs];
                uint32_t b1 = Vs[k + 4][hs];
                mma_tf32(o[nt], a0, a1, a2, a3, b0, b1);
            }
        }
        __syncwarp();
    }

    // normalize + write (tf32-rounded bits) to concat-head layout [B,S,D]
    const float inv0 = 1.0f / l0;
    const float inv1 = 1.0f / l1;
    const int row = q0 + wrow + g;
    uint32_t* Ob = g_attn + (size_t)(b * Sn) * Dn + h * HSn;
    #pragma unroll
    for (int nt = 0; nt < 8; nt++) {
        const int hs = nt * 8 + 2 * t4;
        *(uint2*)&Ob[(size_t)row * Dn + hs] =
            make_uint2(f2tf(o[nt][0] * inv0), f2tf(o[nt][1] * inv0));
        *(uint2*)&Ob[(size_t)(row + 8) * Dn + hs] =
            make_uint2(f2tf(o[nt][2] * inv1), f2tf(o[nt][3] * inv1));
    }
}

// ---------------------------------------------------------------------------
// Kernel 3: output projection (cvt-free, cp.async double-buffered).
// grid = (D/128, B*S/128), block = 256
// ---------------------------------------------------------------------------
__global__ __launch_bounds__(256) void outproj_tc(
    const float* __restrict__ bo,
    float* __restrict__ out)
{
    const int nt0 = blockIdx.x * 128;
    const int m0 = blockIdx.y * 128;
    const uint32_t* A = g_attn + (size_t)m0 * Dn;

    __shared__ uint32_t As[2][128][20];
    __shared__ uint32_t Bs[2][16][136];

    const int tid = threadIdx.x;
    const int lane = tid & 31;
    const int w = tid >> 5;
    const int wm = w >> 1;
    const int wn = w & 1;
    const int g = lane >> 2;
    const int t4 = lane & 3;

    const int ar = tid >> 1;
    const int ac = (tid & 1) * 8;
    const int bk = tid >> 4;
    const int bn = (tid & 15) * 8;
    const uint32_t* Arow = A + (size_t)ar * Dn + ac;
    const uint32_t* Bsrc = g_wot + nt0 + bn;

    float c[2][8][4] = {};

    cp16(&As[0][ar][ac],     Arow);
    cp16(&As[0][ar][ac + 4], Arow + 4);
    cp16(&Bs[0][bk][bn],     Bsrc + (size_t)bk * Dn);
    cp16(&Bs[0][bk][bn + 4], Bsrc + (size_t)bk * Dn + 4);
    CP_COMMIT();
    CP_WAIT0();
    __syncthreads();

    int buf = 0;
    for (int ch = 0; ch < 64; ch++) {
        const bool more = (ch + 1 < 64);
        if (more) {
            const int kc = (ch + 1) * 16;
            const int nb = buf ^ 1;
            cp16(&As[nb][ar][ac],     Arow + kc);
            cp16(&As[nb][ar][ac + 4], Arow + kc + 4);
            cp16(&Bs[nb][bk][bn],     Bsrc + (size_t)(kc + bk) * Dn);
            cp16(&Bs[nb][bk][bn + 4], Bsrc + (size_t)(kc + bk) * Dn + 4);
            CP_COMMIT();
        }

        #pragma unroll
        for (int ks = 0; ks < 2; ks++) {
            const int k = ks * 8 + t4;
            uint32_t a[2][4];
            #pragma unroll
            for (int mt = 0; mt < 2; mt++) {
                const int r = wm * 32 + mt * 16 + g;
                a[mt][0] = As[buf][r][k];
                a[mt][1] = As[buf][r + 8][k];
                a[mt][2] = As[buf][r][k + 4];
                a[mt][3] = As[buf][r + 8][k + 4];
            }
            #pragma unroll
            for (int nt = 0; nt < 8; nt++) {
                const int n = wn * 64 + nt * 8 + g;
                uint32_t b0 = Bs[buf][k][n];
                uint32_t b1 = Bs[buf][k + 4][n];
                mma_tf32(c[0][nt], a[0][0], a[0][1], a[0][2], a[0][3], b0, b1);
                mma_tf32(c[1][nt], a[1][0], a[1][1], a[1][2], a[1][3], b0, b1);
            }
        }

        if (more) CP_WAIT0();
        __syncthreads();
        buf ^= 1;
    }

    float* C = out + (size_t)m0 * Dn + nt0;
    #pragma unroll
    for (int mt = 0; mt < 2; mt++) {
        const int r = wm * 32 + mt * 16 + g;
        #pragma unroll
        for (int nt = 0; nt < 8; nt++) {
            const int n = wn * 64 + nt * 8 + 2 * t4;
            const float2 bias = *(const float2*)&bo[nt0 + n];
            *(float2*)&C[(size_t)r * Dn + n] =
                make_float2(c[mt][nt][0] + bias.x, c[mt][nt][1] + bias.y);
            *(float2*)&C[(size_t)(r + 8) * Dn + n] =
                make_float2(c[mt][nt][2] + bias.x, c[mt][nt][3] + bias.y);
        }
    }
}

// ---------------------------------------------------------------------------
extern "C" void kernel_launch(void* const* d_in, const int* in_sizes, int n_in,
                              void* d_out, int out_size)
{
    const float* X  = (const float*)d_in[0];
    const float* Wq = (const float*)d_in[1];
    const float* Wk = (const float*)d_in[2];
    const float* Wv = (const float*)d_in[3];
    const float* Wo = (const float*)d_in[4];
    const float* bo = (const float*)d_in[5];
    float* out = (float*)d_out;

    uint32_t* xt = nullptr; uint32_t* wt = nullptr; uint32_t* wot = nullptr;
    cudaGetSymbolAddress((void**)&xt,  g_xt);
    cudaGetSymbolAddress((void**)&wt,  g_wt);
    cudaGetSymbolAddress((void**)&wot, g_wot);

    const int nX4 = Bn * Sn * Dn / 4;       // 2M float4
    const int nW4 = WSZ / 4;                // 256K float4
    cvt_tf32<<<1024, 256>>>((const float4*)X,  (uint4*)xt, nX4);
    cvt_tf32<<<512, 256>>>((const float4*)Wq, (uint4*)(wt + 0 * WSZ), nW4);
    cvt_tf32<<<512, 256>>>((const float4*)Wk, (uint4*)(wt + 1 * WSZ), nW4);
    cvt_tf32<<<512, 256>>>((const float4*)Wv, (uint4*)(wt + 2 * WSZ), nW4);
    cvt_tf32<<<512, 256>>>((const float4*)Wo, (uint4*)wot, nW4);

    proj_tc<<<dim3(24, (Bn * Sn) / 128), 256>>>();
    attn_tc<<<dim3(Sn / 128, Bn * Hn), 256>>>();
    outproj_tc<<<dim3(Dn / 128, (Bn * Sn) / 128), 256>>>(bo, out);
}

// round 6
// speedup vs baseline: 3.3509x; 1.0185x over previous
#include <cuda_runtime.h>
#include <cstdint>

// Problem constants
constexpr int Bn = 4;
constexpr int Sn = 2048;
constexpr int Dn = 1024;
constexpr int Hn = 16;
constexpr int HSn = 64;     // head size

constexpr int WSZ = Hn * Dn * HSn;         // one projection weight: 1M elems
constexpr int NX4 = Bn * Sn * Dn / 4;      // X in float4
constexpr int NW4 = WSZ / 4;               // one weight in float4

// Scratch. All hold tf32 BIT PATTERNS (as uint32) except noted.
__device__ uint32_t g_q[Bn * Hn * Sn * HSn];
__device__ uint32_t g_k[Bn * Hn * Sn * HSn];
__device__ uint32_t g_v[Bn * Hn * Sn * HSn];
__device__ uint32_t g_attn[Bn * Sn * Dn];
__device__ uint32_t g_xt[Bn * Sn * Dn];    // X converted
__device__ uint32_t g_wt[3 * WSZ];         // Wq|Wk|Wv converted
__device__ uint32_t g_wot[Dn * Dn];        // Wo converted

// ---------------------------------------------------------------------------
// helpers
// ---------------------------------------------------------------------------
__device__ __forceinline__ uint32_t f2tf(float x) {
    uint32_t r;
    asm("cvt.rna.tf32.f32 %0, %1;" : "=r"(r) : "f"(x));
    return r;
}

__device__ __forceinline__ void mma_tf32(float c[4],
                                         uint32_t a0, uint32_t a1, uint32_t a2, uint32_t a3,
                                         uint32_t b0, uint32_t b1) {
    asm volatile(
        "mma.sync.aligned.m16n8k8.row.col.f32.tf32.tf32.f32 "
        "{%0,%1,%2,%3}, {%4,%5,%6,%7}, {%8,%9}, {%0,%1,%2,%3};\n"
        : "+f"(c[0]), "+f"(c[1]), "+f"(c[2]), "+f"(c[3])
        : "r"(a0), "r"(a1), "r"(a2), "r"(a3), "r"(b0), "r"(b1));
}

__device__ __forceinline__ void cp16(void* smem_dst, const void* gmem_src) {
    uint32_t d = (uint32_t)__cvta_generic_to_shared(smem_dst);
    asm volatile("cp.async.ca.shared.global [%0], [%1], 16;\n"
                 :: "r"(d), "l"(gmem_src));
}
#define CP_COMMIT() asm volatile("cp.async.commit_group;\n" ::: "memory")
#define CP_WAIT0()  asm volatile("cp.async.wait_group 0;\n" ::: "memory")
#define CP_WAIT1()  asm volatile("cp.async.wait_group 1;\n" ::: "memory")

// ---------------------------------------------------------------------------
// Kernel 0: fused fp32 -> tf32 conversion of X, Wq, Wk, Wv, Wo (one launch)
// ---------------------------------------------------------------------------
__global__ __launch_bounds__(256) void cvt_all(
    const float4* __restrict__ X,  const float4* __restrict__ Wq,
    const float4* __restrict__ Wk, const float4* __restrict__ Wv,
    const float4* __restrict__ Wo)
{
    const int total = NX4 + 4 * NW4;
    int i = blockIdx.x * blockDim.x + threadIdx.x;
    const int stride = gridDim.x * blockDim.x;
    for (; i < total; i += stride) {
        const float4* s;
        uint4* d;
        int off;
        if (i < NX4)                { s = X;  d = (uint4*)g_xt;            off = i; }
        else if (i < NX4 + NW4)     { s = Wq; d = (uint4*)g_wt;            off = i - NX4; }
        else if (i < NX4 + 2 * NW4) { s = Wk; d = (uint4*)(g_wt + WSZ);    off = i - NX4 - NW4; }
        else if (i < NX4 + 3 * NW4) { s = Wv; d = (uint4*)(g_wt + 2*WSZ);  off = i - NX4 - 2*NW4; }
        else                        { s = Wo; d = (uint4*)g_wot;           off = i - NX4 - 3*NW4; }
        float4 v = s[off];
        d[off] = make_uint4(f2tf(v.x), f2tf(v.y), f2tf(v.z), f2tf(v.w));
    }
}

// ---------------------------------------------------------------------------
// Kernel 1: merged QKV projection GEMM (cvt-free, cp.async double-buffered).
// Block tile 128x128 (2 heads). 8 warps (4x2), warp tile 32x64. K chunk 16.
// grid = (24, B*S/128), block = 256
// ---------------------------------------------------------------------------
__global__ __launch_bounds__(256) void proj_tc()
{
    const int xx = blockIdx.x;
    const int which = xx >> 3;
    const int h0 = (xx & 7) * 2;
    const int m0 = blockIdx.y * 128;
    const int b = m0 >> 11;
    const int s0 = m0 & 2047;

    uint32_t* outb = (which == 0) ? g_q : (which == 1) ? g_k : g_v;
    const uint32_t* A = g_xt + (size_t)m0 * Dn;
    const uint32_t* B0 = g_wt + (size_t)which * WSZ + (size_t)h0 * Dn * HSn;

    __shared__ uint32_t As[2][128][20];
    __shared__ uint32_t Bs[2][16][136];

    const int tid = threadIdx.x;
    const int lane = tid & 31;
    const int w = tid >> 5;
    const int wm = w >> 1;
    const int wn = w & 1;
    const int g = lane >> 2;
    const int t4 = lane & 3;

    const int ar = tid >> 1;
    const int ac = (tid & 1) * 8;
    const int bk = tid >> 4;
    const int bn = (tid & 15) * 8;
    const uint32_t* Bsrc = B0 + (bn < 64 ? bn : (size_t)Dn * HSn + (bn - 64));
    const uint32_t* Arow = A + (size_t)ar * Dn + ac;

    float c[2][8][4] = {};

    cp16(&As[0][ar][ac],     Arow);
    cp16(&As[0][ar][ac + 4], Arow + 4);
    cp16(&Bs[0][bk][bn],     Bsrc + bk * HSn);
    cp16(&Bs[0][bk][bn + 4], Bsrc + bk * HSn + 4);
    CP_COMMIT();
    CP_WAIT0();
    __syncthreads();

    int buf = 0;
    for (int ch = 0; ch < 64; ch++) {
        const bool more = (ch + 1 < 64);
        if (more) {
            const int kc = (ch + 1) * 16;
            const int nb = buf ^ 1;
            cp16(&As[nb][ar][ac],     Arow + kc);
            cp16(&As[nb][ar][ac + 4], Arow + kc + 4);
            cp16(&Bs[nb][bk][bn],     Bsrc + (kc + bk) * HSn);
            cp16(&Bs[nb][bk][bn + 4], Bsrc + (kc + bk) * HSn + 4);
            CP_COMMIT();
        }

        #pragma unroll
        for (int ks = 0; ks < 2; ks++) {
            const int k = ks * 8 + t4;
            uint32_t a[2][4];
            #pragma unroll
            for (int mt = 0; mt < 2; mt++) {
                const int r = wm * 32 + mt * 16 + g;
                a[mt][0] = As[buf][r][k];
                a[mt][1] = As[buf][r + 8][k];
                a[mt][2] = As[buf][r][k + 4];
                a[mt][3] = As[buf][r + 8][k + 4];
            }
            #pragma unroll
            for (int nt = 0; nt < 8; nt++) {
                const int n = wn * 64 + nt * 8 + g;
                uint32_t b0 = Bs[buf][k][n];
                uint32_t b1 = Bs[buf][k + 4][n];
                mma_tf32(c[0][nt], a[0][0], a[0][1], a[0][2], a[0][3], b0, b1);
                mma_tf32(c[1][nt], a[1][0], a[1][1], a[1][2], a[1][3], b0, b1);
            }
        }

        if (more) CP_WAIT0();
        __syncthreads();
        buf ^= 1;
    }

    const float sc = (which == 0) ? 0.125f : 1.0f;
    uint32_t* O = outb + ((size_t)(b * Hn + h0 + wn) * Sn + s0) * HSn;
    #pragma unroll
    for (int mt = 0; mt < 2; mt++) {
        const int r = wm * 32 + mt * 16 + g;
        #pragma unroll
        for (int nt = 0; nt < 8; nt++) {
            const int hs = nt * 8 + 2 * t4;
            *(uint2*)&O[(size_t)r * HSn + hs] =
                make_uint2(f2tf(c[mt][nt][0] * sc), f2tf(c[mt][nt][1] * sc));
            *(uint2*)&O[(size_t)(r + 8) * HSn + hs] =
                make_uint2(f2tf(c[mt][nt][2] * sc), f2tf(c[mt][nt][3] * sc));
        }
    }
}

// ---------------------------------------------------------------------------
// Kernel 2: causal flash attention. BM=128, BN=32, 8 warps along M.
// 2-stage cp.async double-buffered K/V; P relayout via quad shuffles (no smem).
// grid = (S/128, B*H), block = 256
// ---------------------------------------------------------------------------
__global__ __launch_bounds__(256) void attn_tc()
{
    const int qt = blockIdx.x;
    const int bh = blockIdx.y;
    const int b = bh >> 4;
    const int h = bh & 15;
    const int q0 = qt * 128;

    const uint32_t* Q = g_q + (size_t)(bh * Sn + q0) * HSn;
    const uint32_t* K = g_k + (size_t)bh * Sn * HSn;
    const uint32_t* V = g_v + (size_t)bh * Sn * HSn;

    __shared__ uint32_t Ks[2][32][68];   // B-frag banks 4t4+g (perfect)
    __shared__ uint32_t Vs[2][32][72];   // B-frag banks 8t4+g (perfect)

    const int tid = threadIdx.x;
    const int lane = tid & 31;
    const int w = tid >> 5;
    const int g = lane >> 2;
    const int t4 = lane & 3;
    const int wrow = w * 16;

    // Q fragments: direct bit loads (pre-scaled tf32 from proj)
    uint32_t qf[8][4];
    {
        const uint32_t* Qw = Q + (size_t)(wrow + g) * HSn;
        #pragma unroll
        for (int ks = 0; ks < 8; ks++) {
            const int e = ks * 8 + t4;
            qf[ks][0] = Qw[e];
            qf[ks][1] = Qw[8 * HSn + e];
            qf[ks][2] = Qw[e + 4];
            qf[ks][3] = Qw[8 * HSn + e + 4];
        }
    }

    float o[8][4] = {};
    float m0 = -1e30f, m1 = -1e30f, l0 = 0.0f, l1 = 0.0f;

    const int kn = tid >> 3;            // 0..31
    const int ke = (tid & 7) * 8;
    const int rmax = q0 + wrow + 15;
    const int jmax = 4 * qt + 3;

    // shuffle relayout lanes (C-frag -> A-frag, intra-quad)
    const int srcA = (lane & ~3) | (t4 >> 1);
    const int srcB = srcA + 2;
    const bool hi = (t4 & 1) != 0;

    // prime stage 0 with tile 0
    {
        const uint32_t* kp = K + (size_t)kn * HSn + ke;
        const uint32_t* vp = V + (size_t)kn * HSn + ke;
        cp16(&Ks[0][kn][ke], kp);     cp16(&Ks[0][kn][ke + 4], kp + 4);
        cp16(&Vs[0][kn][ke], vp);     cp16(&Vs[0][kn][ke + 4], vp + 4);
        CP_COMMIT();
    }

    for (int j = 0; j <= jmax; j++) {
        const int st = j & 1;
        const int k0 = j * 32;

        // prefetch next tile into the other stage
        if (j < jmax) {
            const int kc = (j + 1) * 32;
            const uint32_t* kp = K + (size_t)(kc + kn) * HSn + ke;
            const uint32_t* vp = V + (size_t)(kc + kn) * HSn + ke;
            cp16(&Ks[st ^ 1][kn][ke], kp);  cp16(&Ks[st ^ 1][kn][ke + 4], kp + 4);
            cp16(&Vs[st ^ 1][kn][ke], vp);  cp16(&Vs[st ^ 1][kn][ke + 4], vp + 4);
            CP_COMMIT();
            CP_WAIT1();          // current stage's group complete
        } else {
            CP_WAIT0();
        }
        __syncthreads();         // current stage visible block-wide

        if (k0 <= rmax) {
            // S = Q @ K^T
            float s[4][4] = {};
            #pragma unroll
            for (int ks = 0; ks < 8; ks++) {
                const int e = ks * 8 + t4;
                #pragma unroll
                for (int nt = 0; nt < 4; nt++) {
                    const int n = nt * 8 + g;
                    uint32_t b0 = Ks[st][n][e];
                    uint32_t b1 = Ks[st][n][e + 4];
                    mma_tf32(s[nt], qf[ks][0], qf[ks][1], qf[ks][2], qf[ks][3], b0, b1);
                }
            }

            // causal mask
            const int r0g = q0 + wrow + g;
            const int r1g = r0g + 8;
            #pragma unroll
            for (int nt = 0; nt < 4; nt++) {
                const int kc0 = k0 + nt * 8 + 2 * t4;
                if (kc0 > r0g)     s[nt][0] = -1e30f;
                if (kc0 + 1 > r0g) s[nt][1] = -1e30f;
                if (kc0 > r1g)     s[nt][2] = -1e30f;
                if (kc0 + 1 > r1g) s[nt][3] = -1e30f;
            }

            // online softmax (warp-local rows)
            float mx0 = -1e30f, mx1 = -1e30f;
            #pragma unroll
            for (int nt = 0; nt < 4; nt++) {
                mx0 = fmaxf(mx0, fmaxf(s[nt][0], s[nt][1]));
                mx1 = fmaxf(mx1, fmaxf(s[nt][2], s[nt][3]));
            }
            mx0 = fmaxf(mx0, __shfl_xor_sync(0xffffffffu, mx0, 1));
            mx0 = fmaxf(mx0, __shfl_xor_sync(0xffffffffu, mx0, 2));
            mx1 = fmaxf(mx1, __shfl_xor_sync(0xffffffffu, mx1, 1));
            mx1 = fmaxf(mx1, __shfl_xor_sync(0xffffffffu, mx1, 2));

            const float mn0 = fmaxf(m0, mx0);
            const float mn1 = fmaxf(m1, mx1);
            const float al0 = __expf(m0 - mn0);
            const float al1 = __expf(m1 - mn1);
            m0 = mn0; m1 = mn1;

            uint32_t pt[4][4];
            float sum0 = 0.0f, sum1 = 0.0f;
            #pragma unroll
            for (int nt = 0; nt < 4; nt++) {
                float p0 = __expf(s[nt][0] - m0);
                float p1 = __expf(s[nt][1] - m0);
                float p2 = __expf(s[nt][2] - m1);
                float p3 = __expf(s[nt][3] - m1);
                pt[nt][0] = f2tf(p0); pt[nt][1] = f2tf(p1);
                pt[nt][2] = f2tf(p2); pt[nt][3] = f2tf(p3);
                sum0 += __uint_as_float(pt[nt][0]) + __uint_as_float(pt[nt][1]);
                sum1 += __uint_as_float(pt[nt][2]) + __uint_as_float(pt[nt][3]);
            }
            sum0 += __shfl_xor_sync(0xffffffffu, sum0, 1);
            sum0 += __shfl_xor_sync(0xffffffffu, sum0, 2);
            sum1 += __shfl_xor_sync(0xffffffffu, sum1, 1);
            sum1 += __shfl_xor_sync(0xffffffffu, sum1, 2);
            l0 = l0 * al0 + sum0;
            l1 = l1 * al1 + sum1;

            #pragma unroll
            for (int nt = 0; nt < 8; nt++) {
                o[nt][0] *= al0; o[nt][1] *= al0;
                o[nt][2] *= al1; o[nt][3] *= al1;
            }

            // O += P @ V, with C->A relayout via quad shuffles (kstep = ks)
            #pragma unroll
            for (int ks = 0; ks < 4; ks++) {
                uint32_t p0a = __shfl_sync(0xffffffffu, pt[ks][0], srcA);
                uint32_t p1a = __shfl_sync(0xffffffffu, pt[ks][1], srcA);
                uint32_t p2a = __shfl_sync(0xffffffffu, pt[ks][2], srcA);
                uint32_t p3a = __shfl_sync(0xffffffffu, pt[ks][3], srcA);
                uint32_t p0b = __shfl_sync(0xffffffffu, pt[ks][0], srcB);
                uint32_t p1b = __shfl_sync(0xffffffffu, pt[ks][1], srcB);
                uint32_t p2b = __shfl_sync(0xffffffffu, pt[ks][2], srcB);
                uint32_t p3b = __shfl_sync(0xffffffffu, pt[ks][3], srcB);
                uint32_t a0 = hi ? p1a : p0a;   // P[g][ks*8 + t4]
                uint32_t a1 = hi ? p3a : p2a;   // P[g+8][ks*8 + t4]
                uint32_t a2 = hi ? p1b : p0b;   // P[g][ks*8 + t4 + 4]
                uint32_t a3 = hi ? p3b : p2b;   // P[g+8][ks*8 + t4 + 4]
                const int k = ks * 8 + t4;
                #pragma unroll
                for (int nt = 0; nt < 8; nt++) {
                    const int hs = nt * 8 + g;
                    uint32_t b0 = Vs[st][k - t4 + t4][hs];        // Vs[st][ks*8+t4][hs]
                    uint32_t b1 = Vs[st][ks * 8 + t4 + 4][hs];
                    mma_tf32(o[nt], a0, a1, a2, a3, b0, b1);
                    (void)b0;
                }
            }
        }
        __syncthreads();   // stage st free for refill at j+2
    }

    // normalize + write (tf32-rounded bits) to concat-head layout [B,S,D]
    const float inv0 = 1.0f / l0;
    const float inv1 = 1.0f / l1;
    const int row = q0 + wrow + g;
    uint32_t* Ob = g_attn + (size_t)(b * Sn) * Dn + h * HSn;
    #pragma unroll
    for (int nt = 0; nt < 8; nt++) {
        const int hs = nt * 8 + 2 * t4;
        *(uint2*)&Ob[(size_t)row * Dn + hs] =
            make_uint2(f2tf(o[nt][0] * inv0), f2tf(o[nt][1] * inv0));
        *(uint2*)&Ob[(size_t)(row + 8) * Dn + hs] =
            make_uint2(f2tf(o[nt][2] * inv1), f2tf(o[nt][3] * inv1));
    }
}

// ---------------------------------------------------------------------------
// Kernel 3: output projection (cvt-free, cp.async double-buffered).
// grid = (D/128, B*S/128), block = 256
// ---------------------------------------------------------------------------
__global__ __launch_bounds__(256) void outproj_tc(
    const float* __restrict__ bo,
    float* __restrict__ out)
{
    const int nt0 = blockIdx.x * 128;
    const int m0 = blockIdx.y * 128;
    const uint32_t* A = g_attn + (size_t)m0 * Dn;

    __shared__ uint32_t As[2][128][20];
    __shared__ uint32_t Bs[2][16][136];

    const int tid = threadIdx.x;
    const int lane = tid & 31;
    const int w = tid >> 5;
    const int wm = w >> 1;
    const int wn = w & 1;
    const int g = lane >> 2;
    const int t4 = lane & 3;

    const int ar = tid >> 1;
    const int ac = (tid & 1) * 8;
    const int bk = tid >> 4;
    const int bn = (tid & 15) * 8;
    const uint32_t* Arow = A + (size_t)ar * Dn + ac;
    const uint32_t* Bsrc = g_wot + nt0 + bn;

    float c[2][8][4] = {};

    cp16(&As[0][ar][ac],     Arow);
    cp16(&As[0][ar][ac + 4], Arow + 4);
    cp16(&Bs[0][bk][bn],     Bsrc + (size_t)bk * Dn);
    cp16(&Bs[0][bk][bn + 4], Bsrc + (size_t)bk * Dn + 4);
    CP_COMMIT();
    CP_WAIT0();
    __syncthreads();

    int buf = 0;
    for (int ch = 0; ch < 64; ch++) {
        const bool more = (ch + 1 < 64);
        if (more) {
            const int kc = (ch + 1) * 16;
            const int nb = buf ^ 1;
            cp16(&As[nb][ar][ac],     Arow + kc);
            cp16(&As[nb][ar][ac + 4], Arow + kc + 4);
            cp16(&Bs[nb][bk][bn],     Bsrc + (size_t)(kc + bk) * Dn);
            cp16(&Bs[nb][bk][bn + 4], Bsrc + (size_t)(kc + bk) * Dn + 4);
            CP_COMMIT();
        }

        #pragma unroll
        for (int ks = 0; ks < 2; ks++) {
            const int k = ks * 8 + t4;
            uint32_t a[2][4];
            #pragma unroll
            for (int mt = 0; mt < 2; mt++) {
                const int r = wm * 32 + mt * 16 + g;
                a[mt][0] = As[buf][r][k];
                a[mt][1] = As[buf][r + 8][k];
                a[mt][2] = As[buf][r][k + 4];
                a[mt][3] = As[buf][r + 8][k + 4];
            }
            #pragma unroll
            for (int nt = 0; nt < 8; nt++) {
                const int n = wn * 64 + nt * 8 + g;
                uint32_t b0 = Bs[buf][k][n];
                uint32_t b1 = Bs[buf][k + 4][n];
                mma_tf32(c[0][nt], a[0][0], a[0][1], a[0][2], a[0][3], b0, b1);
                mma_tf32(c[1][nt], a[1][0], a[1][1], a[1][2], a[1][3], b0, b1);
            }
        }

        if (more) CP_WAIT0();
        __syncthreads();
        buf ^= 1;
    }

    float* C = out + (size_t)m0 * Dn + nt0;
    #pragma unroll
    for (int mt = 0; mt < 2; mt++) {
        const int r = wm * 32 + mt * 16 + g;
        #pragma unroll
        for (int nt = 0; nt < 8; nt++) {
            const int n = wn * 64 + nt * 8 + 2 * t4;
            const float2 bias = *(const float2*)&bo[nt0 + n];
            *(float2*)&C[(size_t)r * Dn + n] =
                make_float2(c[mt][nt][0] + bias.x, c[mt][nt][1] + bias.y);
            *(float2*)&C[(size_t)(r + 8) * Dn + n] =
                make_float2(c[mt][nt][2] + bias.x, c[mt][nt][3] + bias.y);
        }
    }
}

// ---------------------------------------------------------------------------
extern "C" void kernel_launch(void* const* d_in, const int* in_sizes, int n_in,
                              void* d_out, int out_size)
{
    const float* X  = (const float*)d_in[0];
    const float* Wq = (const float*)d_in[1];
    const float* Wk = (const float*)d_in[2];
    const float* Wv = (const float*)d_in[3];
    const float* Wo = (const float*)d_in[4];
    const float* bo = (const float*)d_in[5];
    float* out = (float*)d_out;

    cvt_all<<<2048, 256>>>((const float4*)X, (const float4*)Wq,
                           (const float4*)Wk, (const float4*)Wv,
                           (const float4*)Wo);
    proj_tc<<<dim3(24, (Bn * Sn) / 128), 256>>>();
    attn_tc<<<dim3(Sn / 128, Bn * Hn), 256>>>();
    outproj_tc<<<dim3(Dn / 128, (Bn * Sn) / 128), 256>>>(bo, out);
}